// round 4
// baseline (speedup 1.0000x reference)
#include <cuda_runtime.h>
#include <cuda_bf16.h>
#include <cstdint>

// LBP layer, fully fused, warp-strip + shuffle design:
//   gray = dot(rgb, [0.2989, 0.587, 0.114])               (zero-padded outside)
//   s(y,x) = #{3x3 nbrs (incl. center): gray >= gray(y,x)}  (s = 0 outside image)
//   lbp(y,x) = 1*s(y-1,x-1)+2*s(y-1,x)+4*s(y-1,x+1)
//            +128*s(y,x-1)           +8*s(y,x+1)
//            +64*s(y+1,x-1)+32*s(y+1,x)+16*s(y+1,x+1)
// Each warp: lane = one s-column, rolls down 16 output rows; s lives only in
// registers, horizontal neighbors exchanged via __shfl. Lanes 1..30 store.
// Fixed shapes: N=32, H=W=512, C=3. Output [N,H,W,1] fp32.

#define OUT_W         30               // output columns per block (warp = 32 s-cols)
#define ROWS_PER_WARP 16
#define NWARPS        8
#define TILE_H        (ROWS_PER_WARP * NWARPS)   // 128
#define G_COLS        34               // gray cols needed: OUT_W + 4
#define G_ROWS        (TILE_H + 4)     // 132
#define G_STRIDE      34               // even -> float2 stores OK
#define NTHREADS      256

__global__ __launch_bounds__(NTHREADS) void lbp_warp_kernel(
    const float* __restrict__ in,   // [N, H, W, 3]
    float* __restrict__ out,        // [N, H, W, 1]
    int H, int W)
{
    __shared__ __align__(8) float g[G_ROWS * G_STRIDE];   // ~17.6 KB

    const int tid  = threadIdx.x;
    const int lane = tid & 31;
    const int wrp  = tid >> 5;
    const int bx = blockIdx.x, by = blockIdx.y, n = blockIdx.z;

    const int x0  = bx * OUT_W;        // first output column of this block
    const int gx0 = x0 - 2;            // gray col of g(:,0)  (even)
    const int gy0 = by * TILE_H - 2;   // gray row of g(0,:)

    const float* __restrict__ base = in + (size_t)n * H * W * 3;

    // ---------------- Phase 1: RGB -> gray into smem (zero outside image) ----
    const bool colsInterior = (gx0 >= 0) && (gx0 + G_COLS <= W);
    if (colsInterior) {
        // float2 pair loads; gx0 even -> (gy*W+gx)*3 floats is 8B-aligned.
        #pragma unroll 4
        for (int idx = tid; idx < G_ROWS * (G_COLS / 2); idx += NTHREADS) {
            const int r  = idx / (G_COLS / 2);
            const int pc = idx - r * (G_COLS / 2);
            const int gy = gy0 + r;
            float g0 = 0.0f, g1 = 0.0f;
            if ((unsigned)gy < (unsigned)H) {
                const int gx = gx0 + 2 * pc;
                const float2* p = (const float2*)(base + ((size_t)gy * W + gx) * 3);
                const float2 v0 = __ldg(p + 0);
                const float2 v1 = __ldg(p + 1);
                const float2 v2 = __ldg(p + 2);
                g0 = fmaf(0.2989f, v0.x, fmaf(0.587f, v0.y, 0.114f * v1.x));
                g1 = fmaf(0.2989f, v1.y, fmaf(0.587f, v2.x, 0.114f * v2.y));
            }
            *(float2*)&g[r * G_STRIDE + 2 * pc] = make_float2(g0, g1);
        }
    } else {
        #pragma unroll 4
        for (int idx = tid; idx < G_ROWS * G_COLS; idx += NTHREADS) {
            const int r = idx / G_COLS;
            const int c = idx - r * G_COLS;
            const int gy = gy0 + r;
            const int gx = gx0 + c;
            float v = 0.0f;
            if ((unsigned)gy < (unsigned)H && (unsigned)gx < (unsigned)W) {
                const float* p = base + ((size_t)gy * W + gx) * 3;
                v = fmaf(0.2989f, __ldg(p), fmaf(0.587f, __ldg(p + 1), 0.114f * __ldg(p + 2)));
            }
            g[r * G_STRIDE + c] = v;
        }
    }
    __syncthreads();

    // ---------------- Phase 2+3 fused: rolling s in registers ----------------
    const int cs = x0 - 1 + lane;                        // this lane's s column
    const bool colValid = (unsigned)cs < (unsigned)W;
    const int r0 = by * TILE_H + wrp * ROWS_PER_WARP;    // first output row

    // gray pointer: smem row (wrp*16) = global row r0-2, col (lane) = cs-1
    const float* gp = &g[(wrp * ROWS_PER_WARP) * G_STRIDE + lane];

    float a0 = gp[0], a1 = gp[1], a2 = gp[2];  gp += G_STRIDE;   // gray row r0-2
    float b0 = gp[0], b1 = gp[1], b2 = gp[2];  gp += G_STRIDE;   // gray row r0-1

    float sl2 = 0.f, sc2 = 0.f, sr2 = 0.f;     // s row (ys-2)
    float sl1 = 0.f, sc1 = 0.f, sr1 = 0.f;     // s row (ys-1)

    const bool doStore = (lane >= 1) && (lane <= 30) && (x0 + lane - 1 < W);
    float* op = out + (size_t)n * H * W + (size_t)r0 * W + (x0 + lane - 1);

    #pragma unroll
    for (int i = 0; i < ROWS_PER_WARP + 2; i++) {
        // load gray row (r0 - 1 + i) + 1  = bottom row of this s stencil
        const float c0 = gp[0], c1 = gp[1], c2 = gp[2];
        gp += G_STRIDE;

        // s at (ys = r0-1+i, cs); center gray = b1; center compare always true
        float cnt = 1.0f;
        cnt += (a0 >= b1) ? 1.0f : 0.0f;
        cnt += (a1 >= b1) ? 1.0f : 0.0f;
        cnt += (a2 >= b1) ? 1.0f : 0.0f;
        cnt += (b0 >= b1) ? 1.0f : 0.0f;
        cnt += (b2 >= b1) ? 1.0f : 0.0f;
        cnt += (c0 >= b1) ? 1.0f : 0.0f;
        cnt += (c1 >= b1) ? 1.0f : 0.0f;
        cnt += (c2 >= b1) ? 1.0f : 0.0f;

        const int ys = r0 - 1 + i;
        const bool rowValid = (unsigned)ys < (unsigned)H;
        const float sc0 = (rowValid && colValid) ? cnt : 0.0f;   // zero-pad s

        const float sl0 = __shfl_up_sync(0xffffffffu, sc0, 1);   // s(ys, cs-1)
        const float sr0 = __shfl_down_sync(0xffffffffu, sc0, 1); // s(ys, cs+1)

        if (i >= 2) {
            // emit lbp at row (ys - 1), col cs
            float v = sl2;                    //   1 * s(ys-2, cs-1)
            v = fmaf(  2.0f, sc2, v);
            v = fmaf(  4.0f, sr2, v);
            v = fmaf(128.0f, sl1, v);
            v = fmaf(  8.0f, sr1, v);
            v = fmaf( 64.0f, sl0, v);
            v = fmaf( 32.0f, sc0, v);
            v = fmaf( 16.0f, sr0, v);
            if (doStore) *op = v;
            op += W;
        }

        sl2 = sl1; sc2 = sc1; sr2 = sr1;
        sl1 = sl0; sc1 = sc0; sr1 = sr0;
        a0 = b0; a1 = b1; a2 = b2;
        b0 = c0; b1 = c1; b2 = c2;
    }
}

extern "C" void kernel_launch(void* const* d_in, const int* in_sizes, int n_in,
                              void* d_out, int out_size)
{
    const float* in = (const float*)d_in[0];
    float* out = (float*)d_out;

    const int H = 512, W = 512;
    const int N = in_sizes[0] / (H * W * 3);

    dim3 grid((W + OUT_W - 1) / OUT_W, H / TILE_H, N);   // 18 x 4 x 32
    lbp_warp_kernel<<<grid, NTHREADS>>>(in, out, H, W);
}